// round 15
// baseline (speedup 1.0000x reference)
#include <cuda_runtime.h>
#include <cstdint>

#define TT   512
#define BB   1024
#define H1   64
#define H2   32
#define G2   128     // 4*H2

// scratch: h1[t][b][j] (values tf32-rounded), j in [0,128): fwd [0,64), rev [64,128)
__device__ float g_h1[(size_t)TT * BB * 128];

// ---- fast activations -----------------------------------------------------
__device__ __forceinline__ float tanh_(float x) {
    float y;
    asm("tanh.approx.f32 %0, %1;" : "=f"(y) : "f"(x));
    return y;
}
__device__ __forceinline__ float sigm(float x) {
    return fmaf(tanh_(x * 0.5f), 0.5f, 0.5f);
}

// ---- tf32 / mma helpers -----------------------------------------------------
__device__ __forceinline__ uint32_t to_tf32(float x) {
    uint32_t r;
    asm("cvt.rna.tf32.f32 %0, %1;" : "=r"(r) : "f"(x));
    return r;
}
__device__ __forceinline__ void mma_tf32(float& c0, float& c1, float& c2, float& c3,
                                         uint32_t a0, uint32_t a1, uint32_t a2, uint32_t a3,
                                         uint32_t b0, uint32_t b1) {
    asm("mma.sync.aligned.m16n8k8.row.col.f32.tf32.tf32.f32 "
        "{%0,%1,%2,%3}, {%4,%5,%6,%7}, {%8,%9}, {%0,%1,%2,%3};"
        : "+f"(c0), "+f"(c1), "+f"(c2), "+f"(c3)
        : "r"(a0), "r"(a1), "r"(a2), "r"(a3), "r"(b0), "r"(b1));
}

// ---- cp.async helpers -------------------------------------------------------
__device__ __forceinline__ uint32_t smem_u32(const void* p) {
    return (uint32_t)__cvta_generic_to_shared(p);
}
#define CP_ASYNC16(dst, src) \
    asm volatile("cp.async.ca.shared.global [%0], [%1], 16;" :: "r"(dst), "l"(src))
#define CP_COMMIT() asm volatile("cp.async.commit_group;")
#define CP_WAIT(n)  asm volatile("cp.async.wait_group %0;" :: "n"(n))

// ---- named barrier ----------------------------------------------------------
__device__ __forceinline__ void barg(int id) {
    asm volatile("bar.sync %0, 128;" :: "r"(id) : "memory");
}

// ---------------------------------------------------------------------------
// Kernel 1: bidirectional layer-1 LSTM, tf32 TC, TWO independent 128-thread
// groups per block (named barriers) so MUFU/cell phases overlap tensor issue.
// grid = (64, 2), block = 256.  Group g handles batches b0+8g..+7 (m16 rows
// 0-7 real, 8-15 zero -> a1=a3=0).  Warp ww owns gate cols 16ww..+15 of each
// gate q => 8 n-tiles x 8 k-chunks = 64 HMMA/warp/step.  Whh frags in regs.
// ---------------------------------------------------------------------------
__global__ __launch_bounds__(256, 1)
void lstm1_tc(const float* __restrict__ x,
              const float* __restrict__ wih_f, const float* __restrict__ whh_f,
              const float* __restrict__ b_f,
              const float* __restrict__ wih_r, const float* __restrict__ whh_r,
              const float* __restrict__ b_r)
{
    const int dir  = blockIdx.y;
    const int tid  = threadIdx.x;
    const int g    = tid >> 7;           // group 0/1
    const int ltid = tid & 127;
    const int ww   = ltid >> 5;          // warp within group
    const int lane = tid & 31;
    const int gid  = lane >> 2;          // batch row 0..7
    const int tig  = lane & 3;
    const int b0g  = blockIdx.x * 16 + 8 * g;

    const float* wih = dir ? wih_r : wih_f;
    const float* whh = dir ? whh_r : whh_f;
    const float* bb  = dir ? b_r  : b_f;

    __shared__ float    sxc[2][8][64];       // per-group x chunk
    __shared__ uint32_t hs[2][2][8][68];     // [group][buf][row][cell] tf32

    // B fragments: n-tile (q, j): n = 64q + 16ww + 8j + gid
    uint32_t bf[4][2][8][2];
#pragma unroll
    for (int q = 0; q < 4; q++)
#pragma unroll
        for (int j = 0; j < 2; j++) {
            const int n = 64 * q + 16 * ww + 8 * j + gid;
#pragma unroll
            for (int kc = 0; kc < 8; kc++) {
                bf[q][j][kc][0] = to_tf32(whh[n * 64 + 8 * kc + tig]);
                bf[q][j][kc][1] = to_tf32(whh[n * 64 + 8 * kc + tig + 4]);
            }
        }

    // this thread's 4 cells: c0+{0,1} (j=0), c0+8+{0,1} (j=1)
    const int c0 = 16 * ww + 2 * tig;
    float wi[4][4], bs4[4][4];
#pragma unroll
    for (int q = 0; q < 4; q++)
#pragma unroll
        for (int e = 0; e < 4; e++) {
            const int cell = c0 + (e >> 1) * 8 + (e & 1);
            wi[q][e]  = wih[64 * q + cell];
            bs4[q][e] = bb[64 * q + cell];
        }

    for (int i = ltid; i < 8 * 68; i += 128) ((uint32_t*)hs[g][0])[i] = 0u;
    float cc[4] = {0.f, 0.f, 0.f, 0.f};
    barg(1 + g);

    for (int tt = 0; tt < TT; ++tt) {
        const int t   = dir ? (TT - 1 - tt) : tt;
        const int cur = tt & 1;
        const int nxt = cur ^ 1;

        if ((tt & 63) == 0) {
            const int tbase = dir ? (448 - tt) : tt;
            const int r  = ltid >> 4;
            const int c4 = (ltid & 15) * 4;
            *(float4*)&sxc[g][r][c4] =
                *(const float4*)(x + (size_t)(b0g + r) * TT + tbase + c4);
            barg(1 + g);
        }
        const int ts = t & 63;

        const float xv = sxc[g][gid][ts];
        float cf[4][2][4];
#pragma unroll
        for (int q = 0; q < 4; q++)
#pragma unroll
            for (int j = 0; j < 2; j++) {
                cf[q][j][0] = fmaf(xv, wi[q][2 * j],     bs4[q][2 * j]);
                cf[q][j][1] = fmaf(xv, wi[q][2 * j + 1], bs4[q][2 * j + 1]);
                cf[q][j][2] = 0.f;
                cf[q][j][3] = 0.f;
            }

#pragma unroll
        for (int kc = 0; kc < 8; kc++) {
            uint32_t a0 = hs[g][cur][gid][8 * kc + tig];
            uint32_t a2 = hs[g][cur][gid][8 * kc + tig + 4];
#pragma unroll
            for (int q = 0; q < 4; q++)
#pragma unroll
                for (int j = 0; j < 2; j++)
                    mma_tf32(cf[q][j][0], cf[q][j][1], cf[q][j][2], cf[q][j][3],
                             a0, 0u, a2, 0u, bf[q][j][kc][0], bf[q][j][kc][1]);
        }

        // cell update (register-resident) for 4 cells
        uint32_t htc[4];
#pragma unroll
        for (int e = 0; e < 4; e++) {
            const int j = e >> 1, l = e & 1;
            float zi = cf[0][j][l], zf = cf[1][j][l];
            float zg = cf[2][j][l], zo = cf[3][j][l];
            cc[e] = sigm(zf) * cc[e] + sigm(zi) * tanh_(zg);
            htc[e] = to_tf32(sigm(zo) * tanh_(cc[e]));
        }

        *(uint2*)&hs[g][nxt][gid][c0]     = make_uint2(htc[0], htc[1]);
        *(uint2*)&hs[g][nxt][gid][c0 + 8] = make_uint2(htc[2], htc[3]);

        float* gout = g_h1 + ((size_t)t * BB + b0g + gid) * 128 + dir * 64;
        *(float2*)(gout + c0) =
            make_float2(__uint_as_float(htc[0]), __uint_as_float(htc[1]));
        *(float2*)(gout + c0 + 8) =
            make_float2(__uint_as_float(htc[2]), __uint_as_float(htc[3]));

        barg(1 + g);
    }
}

// ---------------------------------------------------------------------------
// Kernel 2 (FUSED + PIPELINED): layer-2 forward scan with in-kernel input
// projection.  The h1-part of step t+1 (16 of 20 k-chunks) is computed into
// register acc `cpre` during step t, so the serial h2->h2 path is only
// 4 HMMA + cell.  h1 tiles stream via 4-deep cp.async ring.
// grid = 128, block = 256 (8 warps), 8 batches/block.
// ---------------------------------------------------------------------------
__global__ __launch_bounds__(256, 1)
void lstm2_fused(const float* __restrict__ wih2f, const float* __restrict__ whh2f,
                 const float* __restrict__ b2f,
                 const float* __restrict__ wih2r, const float* __restrict__ b2r,
                 const float* __restrict__ w_fc1, const float* __restrict__ b_fc1,
                 const float* __restrict__ w_out, const float* __restrict__ b_out,
                 float* __restrict__ out)
{
    const int b0   = blockIdx.x * 8;
    const int tid  = threadIdx.x;
    const int w    = tid >> 5;
    const int lane = tid & 31;
    const int gid  = lane >> 2;
    const int tig  = lane & 3;

    __shared__ float    hst[4][8][132];  // h1 tile ring
    __shared__ uint32_t hh2[2][8][36];   // h2 tf32, double-buffered
    __shared__ float    zbuf[8][132];
    __shared__ float    slast[8][64];
    __shared__ float    sfc[8][64];

    // Wcat fragments: warp owns gates [16w, 16w+16) = 2 n-tiles, k = 160
    uint32_t wb[2][20][2];
#pragma unroll
    for (int nt = 0; nt < 2; nt++) {
        const int n = 16 * w + 8 * nt + gid;
#pragma unroll
        for (int kc = 0; kc < 20; kc++) {
            const int k0 = 8 * kc + tig;
            const int k1 = k0 + 4;
            float f0 = (k0 < 128) ? wih2f[n * 128 + k0] : whh2f[n * 32 + k0 - 128];
            float f1 = (k1 < 128) ? wih2f[n * 128 + k1] : whh2f[n * 32 + k1 - 128];
            wb[nt][kc][0] = __float_as_uint(f0);
            wb[nt][kc][1] = __float_as_uint(f1);
        }
    }

    const int cb = tid >> 5;
    const int cj = tid & 31;
    const float bi  = b2f[cj];
    const float bff = b2f[32 + cj];
    const float bgg = b2f[64 + cj];
    const float boo = b2f[96 + cj];
    float cstate = 0.f;
    float hlast  = 0.f;

    for (int i = tid; i < 2 * 8 * 36; i += 256) ((uint32_t*)hh2)[i] = 0u;

    const int sb = tid >> 5;
    const int sk = (tid & 31) * 4;

    // prologue: tiles 0..3
#pragma unroll
    for (int p = 0; p < 4; p++) {
        CP_ASYNC16(smem_u32(&hst[p][sb][sk]),
                   g_h1 + ((size_t)p * BB + b0 + sb) * 128 + sk);
        CP_COMMIT();
    }
    CP_WAIT(3);          // tile 0 complete
    __syncthreads();

    // cpre = h1-part of step 0
    float cpre[2][4] = {{0.f, 0.f, 0.f, 0.f}, {0.f, 0.f, 0.f, 0.f}};
#pragma unroll
    for (int kc = 0; kc < 16; kc++) {
        uint32_t a0 = __float_as_uint(hst[0][gid][8 * kc + tig]);
        uint32_t a2 = __float_as_uint(hst[0][gid][8 * kc + tig + 4]);
        mma_tf32(cpre[0][0], cpre[0][1], cpre[0][2], cpre[0][3],
                 a0, 0u, a2, 0u, wb[0][kc][0], wb[0][kc][1]);
        mma_tf32(cpre[1][0], cpre[1][1], cpre[1][2], cpre[1][3],
                 a0, 0u, a2, 0u, wb[1][kc][0], wb[1][kc][1]);
    }

    for (int t = 0; t < TT; ++t) {
        const int hb = t & 1;

        // z(t) = cpre + h2-part (4 k-chunks, the only h2-dependent work)
        float c[2][4];
#pragma unroll
        for (int nt = 0; nt < 2; nt++)
#pragma unroll
            for (int i = 0; i < 4; i++) c[nt][i] = cpre[nt][i];
#pragma unroll
        for (int kc = 16; kc < 20; kc++) {
            uint32_t a0 = hh2[hb][gid][8 * (kc - 16) + tig];
            uint32_t a2 = hh2[hb][gid][8 * (kc - 16) + tig + 4];
            mma_tf32(c[0][0], c[0][1], c[0][2], c[0][3],
                     a0, 0u, a2, 0u, wb[0][kc][0], wb[0][kc][1]);
            mma_tf32(c[1][0], c[1][1], c[1][2], c[1][3],
                     a0, 0u, a2, 0u, wb[1][kc][0], wb[1][kc][1]);
        }
        *(float2*)&zbuf[gid][16 * w + 2 * tig]     = make_float2(c[0][0], c[0][1]);
        *(float2*)&zbuf[gid][16 * w + 8 + 2 * tig] = make_float2(c[1][0], c[1][1]);

        CP_WAIT(2);          // tile t+1 complete
        __syncthreads();     // zbuf + tile t+1 visible; slot t&3 free

        if (t + 4 < TT) {
            CP_ASYNC16(smem_u32(&hst[t & 3][sb][sk]),
                       g_h1 + ((size_t)(t + 4) * BB + b0 + sb) * 128 + sk);
        }
        CP_COMMIT();

        // h1-part for step t+1 (independent of h2) — fills the cell-phase shadow
        if (t + 1 < TT) {
            const int s1 = (t + 1) & 3;
#pragma unroll
            for (int nt = 0; nt < 2; nt++)
#pragma unroll
                for (int i = 0; i < 4; i++) cpre[nt][i] = 0.f;
#pragma unroll
            for (int kc = 0; kc < 16; kc++) {
                uint32_t a0 = __float_as_uint(hst[s1][gid][8 * kc + tig]);
                uint32_t a2 = __float_as_uint(hst[s1][gid][8 * kc + tig + 4]);
                mma_tf32(cpre[0][0], cpre[0][1], cpre[0][2], cpre[0][3],
                         a0, 0u, a2, 0u, wb[0][kc][0], wb[0][kc][1]);
                mma_tf32(cpre[1][0], cpre[1][1], cpre[1][2], cpre[1][3],
                         a0, 0u, a2, 0u, wb[1][kc][0], wb[1][kc][1]);
            }
        }

        // cell update
        {
            float zi = zbuf[cb][cj]      + bi;
            float zf = zbuf[cb][32 + cj] + bff;
            float zg = zbuf[cb][64 + cj] + bgg;
            float zo = zbuf[cb][96 + cj] + boo;
            cstate = sigm(zf) * cstate + sigm(zi) * tanh_(zg);
            float h = sigm(zo) * tanh_(cstate);
            hlast = h;
            hh2[hb ^ 1][cb][cj] = to_tf32(h);
        }
        __syncthreads();
    }
    // hst[3] = h1[T-1] tile (loaded at iter 507, untouched since).

    // layer-2 reverse: single step at t = T-1 from h=c=0
    {
        const int g2 = tid & 127;
        const int hf = tid >> 7;
        const float brv = b2r[g2];
        float a[4] = {brv, brv, brv, brv};
        const float* wr = wih2r + g2 * G2;
        for (int k = 0; k < G2; k++) {
            float wv = __ldg(wr + k);
#pragma unroll
            for (int b = 0; b < 4; b++)
                a[b] = fmaf(hst[3][hf * 4 + b][k], wv, a[b]);
        }
#pragma unroll
        for (int b = 0; b < 4; b++) zbuf[hf * 4 + b][g2] = a[b];
    }
    __syncthreads();
    {
        float zi = zbuf[cb][cj];
        float zg = zbuf[cb][64 + cj], zo = zbuf[cb][96 + cj];
        float cr = sigm(zi) * tanh_(zg);      // c_prev = 0
        float hr = sigm(zo) * tanh_(cr);
        slast[cb][cj]      = hlast;
        slast[cb][32 + cj] = hr;
    }
    __syncthreads();

    // fc1 (64x64) + relu: 512 items, 2 per thread
#pragma unroll
    for (int rep = 0; rep < 2; rep++) {
        int item = tid + rep * 256;
        int b = item >> 6, o = item & 63;
        float a = b_fc1[o];
        const float* wf = w_fc1 + o * 64;
        for (int k = 0; k < 64; k++) a = fmaf(slast[b][k], __ldg(wf + k), a);
        sfc[b][o] = fmaxf(a, 0.f);
    }
    __syncthreads();

    if (tid < 8) {
        float a = b_out[0];
        for (int k = 0; k < 64; k++) a = fmaf(sfc[tid][k], __ldg(w_out + k), a);
        out[b0 + tid] = sigm(a);
    }
}

// ---------------------------------------------------------------------------
extern "C" void kernel_launch(void* const* d_in, const int* in_sizes, int n_in,
                              void* d_out, int out_size)
{
    (void)in_sizes; (void)n_in; (void)out_size;
    const float* x     = (const float*)d_in[0];
    const float* wih1f = (const float*)d_in[1];
    const float* whh1f = (const float*)d_in[2];
    const float* b1f   = (const float*)d_in[3];
    const float* wih1r = (const float*)d_in[4];
    const float* whh1r = (const float*)d_in[5];
    const float* b1r   = (const float*)d_in[6];
    const float* wih2f = (const float*)d_in[7];
    const float* whh2f = (const float*)d_in[8];
    const float* b2f   = (const float*)d_in[9];
    const float* wih2r = (const float*)d_in[10];
    const float* b2r   = (const float*)d_in[12];
    const float* w_fc1 = (const float*)d_in[13];
    const float* b_fc1 = (const float*)d_in[14];
    const float* w_out = (const float*)d_in[15];
    const float* b_out = (const float*)d_in[16];
    float* out = (float*)d_out;

    lstm1_tc<<<dim3(BB / 16, 2), 256>>>(x, wih1f, whh1f, b1f, wih1r, whh1r, b1r);
    lstm2_fused<<<BB / 8, 256>>>(wih2f, whh2f, b2f, wih2r, b2r,
                                 w_fc1, b_fc1, w_out, b_out, out);
}

// round 16
// speedup vs baseline: 1.5898x; 1.5898x over previous
#include <cuda_runtime.h>
#include <cstdint>

#define TT   512
#define BB   1024
#define H1   64
#define H2   32
#define G2   128     // 4*H2

// h1 scratch, PACKED bf16x2: g_h1p[(t*BB+b)*64 + dir*32 + cellpair]
__device__ uint32_t g_h1p[(size_t)TT * BB * 64];

// ---- fast activations -----------------------------------------------------
__device__ __forceinline__ float tanh_(float x) {
    float y;
    asm("tanh.approx.f32 %0, %1;" : "=f"(y) : "f"(x));
    return y;
}
__device__ __forceinline__ float sigm(float x) {
    return fmaf(tanh_(x * 0.5f), 0.5f, 0.5f);
}

// ---- bf16 helpers -----------------------------------------------------------
__device__ __forceinline__ uint32_t pack_bf16(float lo, float hi) {
    uint32_t r;
    asm("cvt.rn.bf16x2.f32 %0, %1, %2;" : "=r"(r) : "f"(hi), "f"(lo));
    return r;
}
__device__ __forceinline__ float bf_lo(uint32_t u) {
    return __uint_as_float(u << 16);
}
__device__ __forceinline__ float bf_hi(uint32_t u) {
    return __uint_as_float(u & 0xffff0000u);
}
__device__ __forceinline__ void mma_bf16(float& c0, float& c1, float& c2, float& c3,
                                         uint32_t a0, uint32_t a1, uint32_t a2, uint32_t a3,
                                         uint32_t b0, uint32_t b1) {
    asm("mma.sync.aligned.m16n8k16.row.col.f32.bf16.bf16.f32 "
        "{%0,%1,%2,%3}, {%4,%5,%6,%7}, {%8,%9}, {%0,%1,%2,%3};"
        : "+f"(c0), "+f"(c1), "+f"(c2), "+f"(c3)
        : "r"(a0), "r"(a1), "r"(a2), "r"(a3), "r"(b0), "r"(b1));
}

// ---- cp.async helpers -------------------------------------------------------
__device__ __forceinline__ uint32_t smem_u32(const void* p) {
    return (uint32_t)__cvta_generic_to_shared(p);
}
#define CP_ASYNC16(dst, src) \
    asm volatile("cp.async.ca.shared.global [%0], [%1], 16;" :: "r"(dst), "l"(src))
#define CP_COMMIT() asm volatile("cp.async.commit_group;")
#define CP_WAIT(n)  asm volatile("cp.async.wait_group %0;" :: "n"(n))

// ---------------------------------------------------------------------------
// Kernel 1: bidirectional layer-1 LSTM via bf16 m16n8k16 tensor cores.
// grid = (64, 2), block = 256 (8 warps), 16 batches/block (R14 structure).
// Warp w owns gate cols {64q+8w..+7}; 4 gates x 4 k16-chunks = 16 HMMA/step.
// h kept packed bf16x2 in smem (double-buffered, 1 barrier/step) and in g_h1p.
// ---------------------------------------------------------------------------
__global__ __launch_bounds__(256, 1)
void lstm1_tc(const float* __restrict__ x,
              const float* __restrict__ wih_f, const float* __restrict__ whh_f,
              const float* __restrict__ b_f,
              const float* __restrict__ wih_r, const float* __restrict__ whh_r,
              const float* __restrict__ b_r)
{
    const int dir  = blockIdx.y;
    const int b0   = blockIdx.x * 16;
    const int tid  = threadIdx.x;
    const int w    = tid >> 5;
    const int lane = tid & 31;
    const int gid  = lane >> 2;          // 0..7
    const int tig  = lane & 3;

    const float* wih = dir ? wih_r : wih_f;
    const float* whh = dir ? whh_r : whh_f;
    const float* bb  = dir ? b_r  : b_f;

    __shared__ float    sxc[16][64];     // 4 KB x chunk
    __shared__ uint32_t hs[2][16][36];   // packed bf16x2 h (32 pairs + pad)

    // Whh B-fragments (bf16x2) in registers: [gate q][k16-chunk][2]
    uint32_t bf[4][4][2];
#pragma unroll
    for (int q = 0; q < 4; q++) {
        const int n = 64 * q + 8 * w + gid;
#pragma unroll
        for (int kc = 0; kc < 4; kc++) {
            const int k0 = 16 * kc + 2 * tig;
            bf[q][kc][0] = pack_bf16(whh[n * 64 + k0],     whh[n * 64 + k0 + 1]);
            bf[q][kc][1] = pack_bf16(whh[n * 64 + k0 + 8], whh[n * 64 + k0 + 9]);
        }
    }
    const int cell0 = 8 * w + 2 * tig;
    float wi[4][2], bs4[4][2];
#pragma unroll
    for (int q = 0; q < 4; q++) {
        wi[q][0]  = wih[64 * q + cell0];
        wi[q][1]  = wih[64 * q + cell0 + 1];
        bs4[q][0] = bb[64 * q + cell0];
        bs4[q][1] = bb[64 * q + cell0 + 1];
    }

    for (int i = tid; i < 16 * 36; i += 256) ((uint32_t*)hs[0])[i] = 0u;

    // register cell states: (gid,cell0),(gid,cell0+1),(gid+8,cell0),(gid+8,cell0+1)
    float cc[4] = {0.f, 0.f, 0.f, 0.f};
    const int pidx = 4 * w + tig;        // pair index of (cell0, cell0+1)

    __syncthreads();

    for (int tt = 0; tt < TT; ++tt) {
        const int t   = tt ^ (dir ? (TT - 1) : 0);   // dir ? TT-1-tt : tt
        const int cur = tt & 1;
        const int nxt = cur ^ 1;

        if ((tt & 63) == 0) {
            const int tbase = dir ? (448 - tt) : tt;
            for (int i = tid; i < 16 * 64; i += 256) {
                int b = i >> 6, to = i & 63;
                sxc[b][to] = x[(size_t)(b0 + b) * TT + tbase + to];
            }
            __syncthreads();
        }
        const int ts = t & 63;

        const float xv0 = sxc[gid][ts];
        const float xv1 = sxc[gid + 8][ts];
        float c[4][4];
#pragma unroll
        for (int q = 0; q < 4; q++) {
            c[q][0] = fmaf(xv0, wi[q][0], bs4[q][0]);
            c[q][1] = fmaf(xv0, wi[q][1], bs4[q][1]);
            c[q][2] = fmaf(xv1, wi[q][0], bs4[q][0]);
            c[q][3] = fmaf(xv1, wi[q][1], bs4[q][1]);
        }

#pragma unroll
        for (int kc = 0; kc < 4; kc++) {
            uint32_t a0 = hs[cur][gid][8 * kc + tig];
            uint32_t a1 = hs[cur][gid + 8][8 * kc + tig];
            uint32_t a2 = hs[cur][gid][8 * kc + tig + 4];
            uint32_t a3 = hs[cur][gid + 8][8 * kc + tig + 4];
#pragma unroll
            for (int q = 0; q < 4; q++)
                mma_bf16(c[q][0], c[q][1], c[q][2], c[q][3],
                         a0, a1, a2, a3, bf[q][kc][0], bf[q][kc][1]);
        }

        // cell update, register-resident; produce packed bf16 h pairs
#pragma unroll
        for (int j = 0; j < 4; j++) {
            float zi = c[0][j], zf = c[1][j], zg = c[2][j], zo = c[3][j];
            cc[j] = sigm(zf) * cc[j] + sigm(zi) * tanh_(zg);
            c[0][j] = sigm(zo) * tanh_(cc[j]);   // reuse as h
        }
        uint32_t p0 = pack_bf16(c[0][0], c[0][1]);
        uint32_t p1 = pack_bf16(c[0][2], c[0][3]);

        hs[nxt][gid][pidx]     = p0;
        hs[nxt][gid + 8][pidx] = p1;

        g_h1p[((size_t)t * BB + b0 + gid) * 64 + dir * 32 + pidx]     = p0;
        g_h1p[((size_t)t * BB + b0 + gid + 8) * 64 + dir * 32 + pidx] = p1;

        __syncthreads();   // single barrier per step
    }
}

// ---------------------------------------------------------------------------
// Kernel 2 (FUSED): layer-2 forward scan with in-kernel input projection,
// bf16 m16n8k16; + single reverse step + MLP head.  (R14 structure, bf16.)
// grid = 128, block = 256 (8 warps), 8 batches/block.
// Per step: z[8(m16),128] = [h1[t] | h2] (k=160) @ Wcat^T; 10 k16-chunks:
// kc 0-7 from packed h1 tile ring (cp.async), kc 8-9 from packed h2.
// ---------------------------------------------------------------------------
__global__ __launch_bounds__(256, 1)
void lstm2_fused(const float* __restrict__ wih2f, const float* __restrict__ whh2f,
                 const float* __restrict__ b2f,
                 const float* __restrict__ wih2r, const float* __restrict__ b2r,
                 const float* __restrict__ w_fc1, const float* __restrict__ b_fc1,
                 const float* __restrict__ w_out, const float* __restrict__ b_out,
                 float* __restrict__ out)
{
    const int b0   = blockIdx.x * 8;
    const int tid  = threadIdx.x;
    const int w    = tid >> 5;
    const int lane = tid & 31;
    const int gid  = lane >> 2;          // 0..7 (batch row)
    const int tig  = lane & 3;

    __shared__ uint32_t hst[4][8][68];   // h1 tile ring, packed bf16x2
    __shared__ uint32_t hh2[2][8][20];   // h2 packed bf16x2, double-buffered
    __shared__ float    zbuf[8][132];    // gate pre-activations (no bias)
    __shared__ float    slast[8][64];
    __shared__ float    sfc[8][64];

    // Wcat B-fragments (bf16x2): warp owns gates [16w,16w+16) = 2 n-tiles; k=160
    uint32_t wb[2][10][2];
#pragma unroll
    for (int nt = 0; nt < 2; nt++) {
        const int n = 16 * w + 8 * nt + gid;
#pragma unroll
        for (int kc = 0; kc < 10; kc++) {
            const int k0 = 16 * kc + 2 * tig;
            float f0 = (k0 < 128)     ? wih2f[n * 128 + k0]     : whh2f[n * 32 + k0 - 128];
            float f1 = (k0 + 1 < 128) ? wih2f[n * 128 + k0 + 1] : whh2f[n * 32 + k0 - 127];
            float f2 = (k0 + 8 < 128) ? wih2f[n * 128 + k0 + 8] : whh2f[n * 32 + k0 - 120];
            float f3 = (k0 + 9 < 128) ? wih2f[n * 128 + k0 + 9] : whh2f[n * 32 + k0 - 119];
            wb[nt][kc][0] = pack_bf16(f0, f1);
            wb[nt][kc][1] = pack_bf16(f2, f3);
        }
    }

    // cell phase: 128 threads, thread -> (batch pb, cell pair pj2)
    const int pb  = tid >> 4;            // 0..7 (tid<128)
    const int pj  = tid & 15;            // pair index 0..15
    const int pj2 = pj * 2;
    float bi0 = 0.f, bi1 = 0.f, bf0 = 0.f, bf1 = 0.f;
    float bg0 = 0.f, bg1 = 0.f, bo0 = 0.f, bo1 = 0.f;
    if (tid < 128) {
        bi0 = b2f[pj2];      bi1 = b2f[pj2 + 1];
        bf0 = b2f[32 + pj2]; bf1 = b2f[33 + pj2];
        bg0 = b2f[64 + pj2]; bg1 = b2f[65 + pj2];
        bo0 = b2f[96 + pj2]; bo1 = b2f[97 + pj2];
    }
    float cst0 = 0.f, cst1 = 0.f;
    float hl0 = 0.f, hl1 = 0.f;          // final forward h2 (fp32)

    for (int i = tid; i < 2 * 8 * 20; i += 256) ((uint32_t*)hh2)[i] = 0u;

    // staging role (tid<128): batch sb, 4 uint32 at sk
    const int sb = tid >> 4;
    const int sk = (tid & 15) * 4;

    // prologue: issue tiles t=0..2
#pragma unroll
    for (int p = 0; p < 3; p++) {
        if (tid < 128)
            CP_ASYNC16(smem_u32(&hst[p][sb][sk]),
                       g_h1p + ((size_t)p * BB + b0 + sb) * 64 + sk);
        CP_COMMIT();
    }

    for (int t = 0; t < TT; ++t) {
        const int cur = t & 3;
        const int hb  = t & 1;

        CP_WAIT(2);          // tile t complete
        __syncthreads();     // + hh2/zbuf handoff from previous step

        if (t + 3 < TT && tid < 128) {
            CP_ASYNC16(smem_u32(&hst[(t + 3) & 3][sb][sk]),
                       g_h1p + ((size_t)(t + 3) * BB + b0 + sb) * 64 + sk);
        }
        CP_COMMIT();

        // z = [h1 | h2] @ Wcat^T  (m rows 8-15 zero via a1=a3=0)
        float c[2][4] = {{0.f, 0.f, 0.f, 0.f}, {0.f, 0.f, 0.f, 0.f}};
#pragma unroll
        for (int kc = 0; kc < 8; kc++) {
            uint32_t a0 = hst[cur][gid][8 * kc + tig];
            uint32_t a2 = hst[cur][gid][8 * kc + tig + 4];
            mma_bf16(c[0][0], c[0][1], c[0][2], c[0][3],
                     a0, 0u, a2, 0u, wb[0][kc][0], wb[0][kc][1]);
            mma_bf16(c[1][0], c[1][1], c[1][2], c[1][3],
                     a0, 0u, a2, 0u, wb[1][kc][0], wb[1][kc][1]);
        }
#pragma unroll
        for (int kc = 8; kc < 10; kc++) {
            uint32_t a0 = hh2[hb][gid][8 * (kc - 8) + tig];
            uint32_t a2 = hh2[hb][gid][8 * (kc - 8) + tig + 4];
            mma_bf16(c[0][0], c[0][1], c[0][2], c[0][3],
                     a0, 0u, a2, 0u, wb[0][kc][0], wb[0][kc][1]);
            mma_bf16(c[1][0], c[1][1], c[1][2], c[1][3],
                     a0, 0u, a2, 0u, wb[1][kc][0], wb[1][kc][1]);
        }

        *(float2*)&zbuf[gid][16 * w + 2 * tig]     = make_float2(c[0][0], c[0][1]);
        *(float2*)&zbuf[gid][16 * w + 8 + 2 * tig] = make_float2(c[1][0], c[1][1]);
        __syncthreads();

        // cell update: 2 adjacent cells per thread -> packed bf16 pair
        if (tid < 128) {
            float zi0 = zbuf[pb][pj2]      + bi0, zi1 = zbuf[pb][pj2 + 1]  + bi1;
            float zf_ = zbuf[pb][32 + pj2] + bf0, zf1 = zbuf[pb][33 + pj2] + bf1;
            float zg0 = zbuf[pb][64 + pj2] + bg0, zg1 = zbuf[pb][65 + pj2] + bg1;
            float zo0 = zbuf[pb][96 + pj2] + bo0, zo1 = zbuf[pb][97 + pj2] + bo1;
            cst0 = sigm(zf_) * cst0 + sigm(zi0) * tanh_(zg0);
            cst1 = sigm(zf1) * cst1 + sigm(zi1) * tanh_(zg1);
            hl0 = sigm(zo0) * tanh_(cst0);
            hl1 = sigm(zo1) * tanh_(cst1);
            hh2[hb ^ 1][pb][pj] = pack_bf16(hl0, hl1);
        }
        // next iteration's top barrier orders hh2/zbuf handoff
    }

    __syncthreads();
    // hst[3] = h1[T-1] tile (issued at t=508, untouched since).

    // layer-2 reverse: single step at t = T-1 from h=c=0
    {
        const int g2 = tid & 127;
        const int hf = tid >> 7;
        const float brv = b2r[g2];
        float a[4] = {brv, brv, brv, brv};
        const float* wr = wih2r + g2 * G2;
        for (int p = 0; p < 64; p++) {
            float w0 = __ldg(wr + 2 * p);
            float w1 = __ldg(wr + 2 * p + 1);
#pragma unroll
            for (int b = 0; b < 4; b++) {
                uint32_t u = hst[3][hf * 4 + b][p];
                a[b] = fmaf(bf_lo(u), w0, a[b]);
                a[b] = fmaf(bf_hi(u), w1, a[b]);
            }
        }
#pragma unroll
        for (int b = 0; b < 4; b++) zbuf[hf * 4 + b][g2] = a[b];
    }
    __syncthreads();
    if (tid < 128) {
        // reverse cells pj2, pj2+1 for batch pb  (c_prev = 0)
        float zi0 = zbuf[pb][pj2],      zi1 = zbuf[pb][pj2 + 1];
        float zg0 = zbuf[pb][64 + pj2], zg1 = zbuf[pb][65 + pj2];
        float zo0 = zbuf[pb][96 + pj2], zo1 = zbuf[pb][97 + pj2];
        float cr0 = sigm(zi0) * tanh_(zg0);
        float cr1 = sigm(zi1) * tanh_(zg1);
        slast[pb][pj2]          = hl0;
        slast[pb][pj2 + 1]      = hl1;
        slast[pb][32 + pj2]     = sigm(zo0) * tanh_(cr0);
        slast[pb][32 + pj2 + 1] = sigm(zo1) * tanh_(cr1);
    }
    __syncthreads();

    // fc1 (64x64) + relu: 512 items, 2 per thread
#pragma unroll
    for (int rep = 0; rep < 2; rep++) {
        int item = tid + rep * 256;
        int b = item >> 6, o = item & 63;
        float a = b_fc1[o];
        const float* wf = w_fc1 + o * 64;
        for (int k = 0; k < 64; k++) a = fmaf(slast[b][k], __ldg(wf + k), a);
        sfc[b][o] = fmaxf(a, 0.f);
    }
    __syncthreads();

    if (tid < 8) {
        float a = b_out[0];
        for (int k = 0; k < 64; k++) a = fmaf(sfc[tid][k], __ldg(w_out + k), a);
        out[b0 + tid] = sigm(a);
    }
}

// ---------------------------------------------------------------------------
extern "C" void kernel_launch(void* const* d_in, const int* in_sizes, int n_in,
                              void* d_out, int out_size)
{
    (void)in_sizes; (void)n_in; (void)out_size;
    const float* x     = (const float*)d_in[0];
    const float* wih1f = (const float*)d_in[1];
    const float* whh1f = (const float*)d_in[2];
    const float* b1f   = (const float*)d_in[3];
    const float* wih1r = (const float*)d_in[4];
    const float* whh1r = (const float*)d_in[5];
    const float* b1r   = (const float*)d_in[6];
    const float* wih2f = (const float*)d_in[7];
    const float* whh2f = (const float*)d_in[8];
    const float* b2f   = (const float*)d_in[9];
    const float* wih2r = (const float*)d_in[10];
    const float* b2r   = (const float*)d_in[12];
    const float* w_fc1 = (const float*)d_in[13];
    const float* b_fc1 = (const float*)d_in[14];
    const float* w_out = (const float*)d_in[15];
    const float* b_out = (const float*)d_in[16];
    float* out = (float*)d_out;

    lstm1_tc<<<dim3(BB / 16, 2), 256>>>(x, wih1f, whh1f, b1f, wih1r, whh1r, b1r);
    lstm2_fused<<<BB / 8, 256>>>(wih2f, whh2f, b2f, wih2r, b2r,
                                 w_fc1, b_fc1, w_out, b_out, out);
}